// round 17
// baseline (speedup 1.0000x reference)
#include <cuda_runtime.h>
#include <cstdint>

#define NN 100000
#define EE 1600000
#define SCAN_BLK 2048          // elements per scan block (256 threads x 8)
#define MAX_PARTS 128

typedef unsigned long long u64;

// f32x2 packed helpers (sm_100+): bit-exact 2-wide fp32 FMA, 2x FFMA throughput
__device__ __forceinline__ u64 pk2(float x) {
    u64 r; asm("mov.b64 %0, {%1, %1};" : "=l"(r) : "f"(x)); return r;
}
__device__ __forceinline__ void fma2(u64& d, u64 a, u64 b) {
    asm("fma.rn.f32x2 %0, %1, %2, %0;" : "+l"(d) : "l"(a), "l"(b));
}
__device__ __forceinline__ void unpk2(u64 v, float& lo, float& hi) {
    asm("mov.b64 {%0, %1}, %2;" : "=f"(lo), "=f"(hi) : "l"(v));
}

// ---------------- scratch (device globals; no allocations allowed) -------------
__device__ int   g_cnt[NN];            // in-degree (edges only)
__device__ int   g_rowptr[NN + 1];     // CSR row pointers (by dst)
__device__ int   g_cursor[NN];         // fill cursors
__device__ int   g_csrc[EE];           // CSR src indices
__device__ int   g_part[MAX_PARTS];    // scan partials
__device__ float g_dinv[NN];
__device__ float g_T[NN * 64];         // Ts = (h @ W) * dinv[row]
__device__ float g_H[4 * NN * 64];     // per-layer post-relu features
__device__ float g_M[64 * 64];         // Wq @ Wk^T
__device__ float g_scores[4 * NN];

// ---------------- degree / CSR build --------------------------------------------
__global__ void k_zerocnt(int n) {
    int i = blockIdx.x * 256 + threadIdx.x;
    if (i < n) g_cnt[i] = 0;
}

__global__ void k_count(const int* __restrict__ ei, int E) {
    int e = blockIdx.x * 256 + threadIdx.x;
    if (e < E) atomicAdd(&g_cnt[ei[E + e]], 1);
}

// ---- scan phase 1: per-block reduce + dinv  -------------------------------------
__global__ void __launch_bounds__(256) k_scan1(int n) {
    int tid = threadIdx.x;
    int base = blockIdx.x * SCAN_BLK + tid * 8;
    int s = 0;
#pragma unroll
    for (int k = 0; k < 8; k++) {
        int i = base + k;
        if (i < n) {
            int c = g_cnt[i];
            s += c;
            g_dinv[i] = rsqrtf((float)(c + 1));   // +1 self loop
        }
    }
#pragma unroll
    for (int off = 16; off; off >>= 1) s += __shfl_xor_sync(0xffffffffu, s, off);
    __shared__ int sw[8];
    if ((tid & 31) == 0) sw[tid >> 5] = s;
    __syncthreads();
    if (tid == 0) {
        int t = 0;
#pragma unroll
        for (int w = 0; w < 8; w++) t += sw[w];
        g_part[blockIdx.x] = t;
    }
}

// ---- scan phase 2: exclusive scan of partials (single small block) --------------
__global__ void k_scan2(int nparts, int n) {
    __shared__ int sh[MAX_PARTS];
    int tid = threadIdx.x;
    sh[tid] = (tid < nparts) ? g_part[tid] : 0;
    __syncthreads();
    for (int off = 1; off < MAX_PARTS; off <<= 1) {
        int t = (tid >= off) ? sh[tid - off] : 0;
        __syncthreads();
        sh[tid] += t;
        __syncthreads();
    }
    if (tid < nparts) g_part[tid] = (tid ? sh[tid - 1] : 0);
    if (tid == MAX_PARTS - 1) g_rowptr[n] = sh[MAX_PARTS - 1];
}

// ---- scan phase 3: block-local exclusive scan + offset -> rowptr/cursor ---------
__global__ void __launch_bounds__(256) k_scan3(int n) {
    __shared__ int sw[8];
    int tid = threadIdx.x;
    int base = blockIdx.x * SCAN_BLK + tid * 8;
    int v[8];
    int s = 0;
#pragma unroll
    for (int k = 0; k < 8; k++) {
        int i = base + k;
        int c = (i < n) ? g_cnt[i] : 0;
        v[k] = s;          // exclusive within thread
        s += c;
    }
    int lane = tid & 31, w = tid >> 5;
    int incl = s;
#pragma unroll
    for (int off = 1; off < 32; off <<= 1) {
        int t = __shfl_up_sync(0xffffffffu, incl, off);
        if (lane >= off) incl += t;
    }
    if (lane == 31) sw[w] = incl;
    __syncthreads();
    int wofs = 0;
    if (tid < 8) {
        int t = sw[tid];
        int e = 0;
        for (int k = 0; k < 8; k++) { int tv = __shfl_sync(0xffu, t, k); if (k < tid) e += tv; }
        sw[tid] = e;
        (void)e;
    }
    __syncthreads();
    wofs = sw[w];
    int texcl = wofs + incl - s;                 // exclusive across block
    int blkofs = g_part[blockIdx.x];
#pragma unroll
    for (int k = 0; k < 8; k++) {
        int i = base + k;
        if (i < n) {
            int p = blkofs + texcl + v[k];
            g_rowptr[i] = p;
            g_cursor[i] = p;
        }
    }
}

__global__ void k_fill(const int* __restrict__ ei, int E) {
    int e = blockIdx.x * 256 + threadIdx.x;
    if (e < E) {
        int s = ei[e];
        int d = ei[E + e];
        int pos = atomicAdd(&g_cursor[d], 1);
        g_csrc[pos] = s;
    }
}

// ---------------- M = Wq @ Wk^T  (64x64), SMEM-staged ----------------------------
__global__ void __launch_bounds__(1024) k_M(const float* __restrict__ Wq,
                                            const float* __restrict__ Wk) {
    __shared__ float sq[64 * 64];
    __shared__ float sk[64 * 64];
    int tid = threadIdx.x;
    for (int i = tid; i < 4096; i += 1024) { sq[i] = Wq[i]; sk[i] = Wk[i]; }
    __syncthreads();
    int idx = blockIdx.x * 1024 + tid;
    int d = idx >> 6, j = idx & 63;
    float acc = 0.f;
#pragma unroll
    for (int e = 0; e < 64; e++) acc = fmaf(sq[d * 64 + e], sk[j * 64 + e], acc);
    g_M[idx] = acc;
}

// ---------------- tall-skinny GEMM (f32x2, 16 cols x 8 rows, row-range) ----------
template <int K>
__global__ void __launch_bounds__(256, 4) k_gemm(const float* __restrict__ Aext,
                                                 int srcLayer,
                                                 const float* __restrict__ W,
                                                 int nrows, int rowStart, int rowEnd) {
    constexpr int NCH = K / 64;
    __shared__ float shW[64 * 64];    // 16KB: one 64-k chunk of W
    __shared__ float shA[128 * 64];   // 32KB: 128 rows x 64-k chunk
    int tid = threadIdx.x;
    int t = tid & 15, g = tid >> 4;
    int rowBase = rowStart + blockIdx.x * 128;

    const float* A = (srcLayer < 0) ? Aext : (g_H + (size_t)srcLayer * nrows * 64);
    const float4* A4 = (const float4*)A;
    const float4* W4 = (const float4*)W;
    const int q = K / 4;

    u64 acc[8][2];
#pragma unroll
    for (int rr = 0; rr < 8; rr++) { acc[rr][0] = 0ull; acc[rr][1] = 0ull; }

    for (int ch = 0; ch < NCH; ch++) {
        if (ch > 0) __syncthreads();
        {
            float4* sW4 = (float4*)shW;
            for (int i = tid; i < 1024; i += 256) sW4[i] = W4[ch * 1024 + i];
        }
        {
            float4* sA4 = (float4*)shA;
            for (int i = tid; i < 2048; i += 256) {
                int r = i >> 4;
                int row = rowBase + r;
                float4 v = make_float4(0.f, 0.f, 0.f, 0.f);
                if (row < rowEnd) v = A4[(size_t)row * q + ch * 16 + (i & 15)];
                sA4[i] = v;
            }
        }
        __syncthreads();

#pragma unroll 4
        for (int k = 0; k < 64; k += 4) {
            ulonglong2 w0 = *(const ulonglong2*)&shW[(k + 0) * 64 + t * 4];
            ulonglong2 w1 = *(const ulonglong2*)&shW[(k + 1) * 64 + t * 4];
            ulonglong2 w2 = *(const ulonglong2*)&shW[(k + 2) * 64 + t * 4];
            ulonglong2 w3 = *(const ulonglong2*)&shW[(k + 3) * 64 + t * 4];
#pragma unroll
            for (int rr = 0; rr < 8; rr++) {
                float4 a4 = *(const float4*)&shA[(g * 8 + rr) * 64 + k];
                u64 a0 = pk2(a4.x), a1 = pk2(a4.y), a2 = pk2(a4.z), a3 = pk2(a4.w);
                fma2(acc[rr][0], a0, w0.x); fma2(acc[rr][1], a0, w0.y);
                fma2(acc[rr][0], a1, w1.x); fma2(acc[rr][1], a1, w1.y);
                fma2(acc[rr][0], a2, w2.x); fma2(acc[rr][1], a2, w2.y);
                fma2(acc[rr][0], a3, w3.x); fma2(acc[rr][1], a3, w3.y);
            }
        }
    }

#pragma unroll
    for (int rr = 0; rr < 8; rr++) {
        int row = rowBase + g * 8 + rr;
        if (row < rowEnd) {
            float dv = g_dinv[row];
            float4 v;
            unpk2(acc[rr][0], v.x, v.y);
            unpk2(acc[rr][1], v.z, v.w);
            v.x *= dv; v.y *= dv; v.z *= dv; v.w *= dv;
            ((float4*)g_T)[(size_t)row * 16 + t] = v;
        }
    }
}

// ---------------- scores as GEMM (f32x2, 16x8) + fused dot, row slice ------------
__global__ void __launch_bounds__(256, 4) k_score(int base, int limit) {
    __shared__ float shW[64 * 64];
    __shared__ float shA[128 * 64];
    int tid = threadIdx.x;
    int t = tid & 15, g = tid >> 4;
    int rowBase = base + blockIdx.x * 128;

    {
        float4* sW4 = (float4*)shW;
        const float4* M4 = (const float4*)g_M;
        for (int i = tid; i < 1024; i += 256) sW4[i] = M4[i];
    }
    {
        float4* sA4 = (float4*)shA;
        const float4* A4 = (const float4*)g_H;
        for (int i = tid; i < 2048; i += 256) {
            int r = i >> 4;
            int row = rowBase + r;
            float4 v = make_float4(0.f, 0.f, 0.f, 0.f);
            if (row < limit) v = A4[(size_t)row * 16 + (i & 15)];
            sA4[i] = v;
        }
    }
    __syncthreads();

    u64 acc[8][2];
#pragma unroll
    for (int rr = 0; rr < 8; rr++) { acc[rr][0] = 0ull; acc[rr][1] = 0ull; }

#pragma unroll 4
    for (int k = 0; k < 64; k += 4) {
        ulonglong2 w0 = *(const ulonglong2*)&shW[(k + 0) * 64 + t * 4];
        ulonglong2 w1 = *(const ulonglong2*)&shW[(k + 1) * 64 + t * 4];
        ulonglong2 w2 = *(const ulonglong2*)&shW[(k + 2) * 64 + t * 4];
        ulonglong2 w3 = *(const ulonglong2*)&shW[(k + 3) * 64 + t * 4];
#pragma unroll
        for (int rr = 0; rr < 8; rr++) {
            float4 a4 = *(const float4*)&shA[(g * 8 + rr) * 64 + k];
            u64 a0 = pk2(a4.x), a1 = pk2(a4.y), a2 = pk2(a4.z), a3 = pk2(a4.w);
            fma2(acc[rr][0], a0, w0.x); fma2(acc[rr][1], a0, w0.y);
            fma2(acc[rr][0], a1, w1.x); fma2(acc[rr][1], a1, w1.y);
            fma2(acc[rr][0], a2, w2.x); fma2(acc[rr][1], a2, w2.y);
            fma2(acc[rr][0], a3, w3.x); fma2(acc[rr][1], a3, w3.y);
        }
    }

#pragma unroll
    for (int rr = 0; rr < 8; rr++) {
        int row = rowBase + g * 8 + rr;
        float4 h4 = *(const float4*)&shA[(g * 8 + rr) * 64 + t * 4];
        float4 pv;
        unpk2(acc[rr][0], pv.x, pv.y);
        unpk2(acc[rr][1], pv.z, pv.w);
        float p = pv.x * h4.x + pv.y * h4.y + pv.z * h4.z + pv.w * h4.w;
        p += __shfl_xor_sync(0xffffffffu, p, 1);
        p += __shfl_xor_sync(0xffffffffu, p, 2);
        p += __shfl_xor_sync(0xffffffffu, p, 4);
        p += __shfl_xor_sync(0xffffffffu, p, 8);
        if (t == 0 && row < limit) g_scores[row] = p * 10.0f;  // 1/TEMP
    }
}

// ---------------- CSR gather: float4 lanes, 2 edges/step, 16-edge unroll ---------
// warp per node; lane = sub*16+col; sub handles edges j+sub (step 2); col covers
// 16B of the 256B row. Combine halves with one shfl_xor(16) set at the end.
__global__ void __launch_bounds__(256) k_gather(int layer, const float* __restrict__ b,
                                                int n, int nodeStart, int nodeEnd) {
    int warp = nodeStart + ((blockIdx.x * 256 + threadIdx.x) >> 5);
    int lane = threadIdx.x & 31;
    int sub = lane >> 4, col = lane & 15;
    if (warp >= nodeEnd) return;
    int start = g_rowptr[warp];
    int end = g_rowptr[warp + 1];
    const float4* T4 = (const float4*)g_T;
    float4 a = make_float4(0.f, 0.f, 0.f, 0.f);
    int j = start;
    for (; j + 16 <= end; j += 16) {
#pragma unroll
        for (int u = 0; u < 8; u++) {
            int s = g_csrc[j + 2 * u + sub];
            float4 v = T4[(size_t)s * 16 + col];
            a.x += v.x; a.y += v.y; a.z += v.z; a.w += v.w;
        }
    }
    for (; j + 2 <= end; j += 2) {
        int s = g_csrc[j + sub];
        float4 v = T4[(size_t)s * 16 + col];
        a.x += v.x; a.y += v.y; a.z += v.z; a.w += v.w;
    }
    if (j < end && sub == 0) {
        int s = g_csrc[j];
        float4 v = T4[(size_t)s * 16 + col];
        a.x += v.x; a.y += v.y; a.z += v.z; a.w += v.w;
    }
    // combine the two 16-lane halves
    a.x += __shfl_xor_sync(0xffffffffu, a.x, 16);
    a.y += __shfl_xor_sync(0xffffffffu, a.y, 16);
    a.z += __shfl_xor_sync(0xffffffffu, a.z, 16);
    a.w += __shfl_xor_sync(0xffffffffu, a.w, 16);
    if (sub == 0) {
        float4 t = T4[(size_t)warp * 16 + col];     // self term Ts[d]
        float dv = g_dinv[warp];
        float4 bb = ((const float4*)b)[col];
        float4 h;
        h.x = fmaxf(fmaf(a.x + t.x, dv, bb.x), 0.f);
        h.y = fmaxf(fmaf(a.y + t.y, dv, bb.y), 0.f);
        h.z = fmaxf(fmaf(a.z + t.z, dv, bb.z), 0.f);
        h.w = fmaxf(fmaf(a.w + t.w, dv, bb.w), 0.f);
        ((float4*)g_H)[(size_t)layer * n * 16 + (size_t)warp * 16 + col] = h;
    }
}

// ---------------- fused softmax + weighted sum + output GEMM (node range) --------
__global__ void __launch_bounds__(128) k_final(const float* __restrict__ Wout,
                                               const float* __restrict__ bout,
                                               float* __restrict__ out, int n,
                                               int nodeStart, int nodeEnd) {
    __shared__ float shW[64 * 40];
    __shared__ float shB[40];
    __shared__ float shS[16][64];
    int tid = threadIdx.x;
    for (int i = tid; i < 64 * 40; i += 128) shW[i] = Wout[i];
    if (tid < 40) shB[tid] = bout[tid];

    int nodeBase = nodeStart + blockIdx.x * 16;
    int nl = tid >> 3;
    int dg = tid & 7;
    int node = nodeBase + nl;
    if (node < nodeEnd) {
        float s0 = g_scores[node];
        float s1 = g_scores[n + node];
        float s2 = g_scores[2 * n + node];
        float s3 = g_scores[3 * n + node];
        float m = fmaxf(fmaxf(s0, s1), fmaxf(s2, s3));
        float e0 = __expf(s0 - m), e1 = __expf(s1 - m);
        float e2 = __expf(s2 - m), e3 = __expf(s3 - m);
        float inv = 1.0f / (e0 + e1 + e2 + e3);
        e0 *= inv; e1 *= inv; e2 *= inv; e3 *= inv;
        size_t nh = (size_t)n * 64;
        size_t off0 = (size_t)node * 64 + dg * 8;
#pragma unroll
        for (int dd = 0; dd < 8; dd++) {
            size_t o = off0 + dd;
            float v = e0 * g_H[o] + e1 * g_H[nh + o] + e2 * g_H[2 * nh + o] + e3 * g_H[3 * nh + o];
            shS[nl][dg * 8 + dd] = v;
        }
    }
    __syncthreads();

    for (int o = tid; o < 16 * 40; o += 128) {
        int n2 = o / 40, c = o - n2 * 40;
        int node2 = nodeBase + n2;
        if (node2 < nodeEnd) {
            float acc = shB[c];
#pragma unroll
            for (int k = 0; k < 64; k++) acc = fmaf(shS[n2][k], shW[k * 40 + c], acc);
            out[(size_t)node2 * 40 + c] = acc;
        }
    }
}

// ---------------- launch: 3-stream pipelined fork/join ---------------------------
extern "C" void kernel_launch(void* const* d_in, const int* in_sizes, int n_in,
                              void* d_out, int out_size) {
    const float* x    = (const float*)d_in[0];
    const int*   ei   = (const int*)d_in[1];   // int32 on device
    const float* W0   = (const float*)d_in[2];
    const float* b0   = (const float*)d_in[3];
    const float* Ws   = (const float*)d_in[4];
    const float* bs   = (const float*)d_in[5];
    const float* Wq   = (const float*)d_in[6];
    const float* Wk   = (const float*)d_in[7];
    const float* Wout = (const float*)d_in[8];
    const float* bout = (const float*)d_in[9];
    float* out        = (float*)d_out;

    int n = in_sizes[0] / 128;
    int E = in_sizes[1] / 2;
    int nparts = (n + SCAN_BLK - 1) / SCAN_BLK;

    int nh0 = ((n / 2) + 127) / 128 * 128;
    if (nh0 > n) nh0 = n;
    int gB0 = (nh0 + 127) / 128;
    int gB1 = (n - nh0 + 127) / 128;
    int gaB0 = (nh0 * 32 + 255) / 256;
    int gaB1 = ((n - nh0) * 32 + 255) / 256;
    int scoreBlocks = (n + 127) / 128;
    int sc3aB = (nh0 + 127) / 128;
    int sc3bB = (n - nh0 + 127) / 128;
    int fB0 = (nh0 + 15) / 16;
    int fB1 = (n - nh0 + 15) / 16;

    static cudaStream_t sB = nullptr, sC = nullptr;
    static cudaEvent_t evStart, evScan1, evFill;
    static cudaEvent_t eGm[4][2], eGa[4][2], eS[3], eS3a, eS3b, eFin1;
    if (!sB) {
        cudaStreamCreateWithFlags(&sB, cudaStreamNonBlocking);
        cudaStreamCreateWithFlags(&sC, cudaStreamNonBlocking);
        cudaEventCreateWithFlags(&evStart, cudaEventDisableTiming);
        cudaEventCreateWithFlags(&evScan1, cudaEventDisableTiming);
        cudaEventCreateWithFlags(&evFill, cudaEventDisableTiming);
        for (int l = 0; l < 4; l++) {
            cudaEventCreateWithFlags(&eGm[l][0], cudaEventDisableTiming);
            cudaEventCreateWithFlags(&eGm[l][1], cudaEventDisableTiming);
            cudaEventCreateWithFlags(&eGa[l][0], cudaEventDisableTiming);
            cudaEventCreateWithFlags(&eGa[l][1], cudaEventDisableTiming);
        }
        for (int l = 0; l < 3; l++) cudaEventCreateWithFlags(&eS[l], cudaEventDisableTiming);
        cudaEventCreateWithFlags(&eS3a, cudaEventDisableTiming);
        cudaEventCreateWithFlags(&eS3b, cudaEventDisableTiming);
        cudaEventCreateWithFlags(&eFin1, cudaEventDisableTiming);
    }

    // ---- head on stream A (default): degree + dinv ----
    k_zerocnt<<<(n + 255) / 256, 256>>>(n);
    k_count<<<(E + 255) / 256, 256>>>(ei, E);
    k_scan1<<<nparts, 256>>>(n);
    cudaEventRecord(evScan1, 0);
    cudaEventRecord(evStart, 0);

    // ---- stream C (aux): k_M + CSR finish ----
    cudaStreamWaitEvent(sC, evStart, 0);
    k_M<<<4, 1024, 0, sC>>>(Wq, Wk);
    k_scan2<<<1, MAX_PARTS, 0, sC>>>(nparts, n);
    k_scan3<<<nparts, 256, 0, sC>>>(n);
    k_fill<<<(E + 255) / 256, 256, 0, sC>>>(ei, E);
    cudaEventRecord(evFill, sC);

    // ---- gemm0 split across A and B ----
    cudaStreamWaitEvent(sB, evScan1, 0);
    k_gemm<128><<<gB0, 256>>>(x, -1, W0, n, 0, nh0);                 // A
    cudaEventRecord(eGm[0][0], 0);
    k_gemm<128><<<gB1, 256, 0, sB>>>(x, -1, W0, n, nh0, n);          // B
    cudaEventRecord(eGm[0][1], sB);

    // ---- pipelined layer loop ----
    for (int l = 0; l < 4; l++) {
        const float* b = (l == 0) ? b0 : (bs + (size_t)(l - 1) * 64);

        cudaStreamWaitEvent(0, eGm[l][1], 0);
        if (l == 0) cudaStreamWaitEvent(0, evFill, 0);
        k_gather<<<gaB0, 256>>>(l, b, n, 0, nh0);
        cudaEventRecord(eGa[l][0], 0);

        cudaStreamWaitEvent(sB, eGm[l][0], 0);
        if (l == 0) cudaStreamWaitEvent(sB, evFill, 0);
        k_gather<<<gaB1, 256, 0, sB>>>(l, b, n, nh0, n);
        cudaEventRecord(eGa[l][1], sB);

        if (l < 3) {
            // score_l on C (needs both halves); gemm_{l+1} per half
            cudaStreamWaitEvent(sC, eGa[l][0], 0);
            cudaStreamWaitEvent(sC, eGa[l][1], 0);
            k_score<<<scoreBlocks, 256, 0, sC>>>(l * n, (l + 1) * n);
            cudaEventRecord(eS[l], sC);

            const float* W = Ws + (size_t)l * 64 * 64;
            k_gemm<64><<<gB0, 256>>>(nullptr, l, W, n, 0, nh0);        // A
            cudaEventRecord(eGm[l + 1][0], 0);
            k_gemm<64><<<gB1, 256, 0, sB>>>(nullptr, l, W, n, nh0, n); // B
            cudaEventRecord(eGm[l + 1][1], sB);
        }
    }

    // ---- layer-3 scores split per half on C, pipelined with gather3 halves ----
    cudaStreamWaitEvent(sC, eGa[3][0], 0);
    k_score<<<sc3aB, 256, 0, sC>>>(3 * n, 3 * n + nh0);
    cudaEventRecord(eS3a, sC);
    cudaStreamWaitEvent(sC, eGa[3][1], 0);
    k_score<<<sc3bB, 256, 0, sC>>>(3 * n + nh0, 4 * n);
    cudaEventRecord(eS3b, sC);

    // ---- final split per half: h0 on A (after eS3a), h1 on B (after eS3b) ----
    for (int l = 0; l < 3; l++) cudaStreamWaitEvent(0, eS[l], 0);
    cudaStreamWaitEvent(0, eS3a, 0);
    k_final<<<fB0, 128>>>(Wout, bout, out, n, 0, nh0);

    for (int l = 0; l < 3; l++) cudaStreamWaitEvent(sB, eS[l], 0);
    cudaStreamWaitEvent(sB, eS3b, 0);
    k_final<<<fB1, 128, 0, sB>>>(Wout, bout, out, n, nh0, n);
    cudaEventRecord(eFin1, sB);
    cudaStreamWaitEvent(0, eFin1, 0);   // join so stream A (capture origin) ends last
}